// round 15
// baseline (speedup 1.0000x reference)
#include <cuda_runtime.h>

// Problem dims
#define A_DIM 32
#define R_DIM 2
#define T_DIM 4
#define S_DIM 14
#define F_DIM 3072
#define RB_DIM 256
#define NSITES (A_DIM * S_DIM * RB_DIM)   // 114688

#define BETA 2.71765f                      // 4.4492*ER^2 + 4.5655*ER + 1.2982, ER=0.25
#define SNR_LIN 10.0f
#define SQH 0.70710678118654752f

// Scratch. g_R statically zero; K5 re-zeroes it each launch (replay-safe).
// g_R layout (16): [0..3] diag real R_tt ; [4+2p,5+2p] complex R_tu for
// pairs p: (0,1),(0,2),(0,3),(1,2),(1,3),(2,3)
__device__ float2 g_avg[NSITES * 8];       // [site][r*4+t], site = (a*14+s)*256+rb
__device__ float  g_R[16] = {};
__device__ float  g_rate[RB_DIM * 32];     // per (rb, c) rate

// ---------------------------------------------------------------------------
// K1: warp-autonomous RB-average. 896 blocks x 256 thr; each WARP owns
// (as, r, seg): for t=0..3 loads 3 coalesced float4 per thread per array,
// hsums, and shuffle-regroups so lane i gets RB (seg*32+i). No block barrier
// in the load path. Per-thread Gram + butterfly + 16 atomics per block.
// ---------------------------------------------------------------------------
__global__ void __launch_bounds__(256, 4) k1_rb_average(const float* __restrict__ hre,
                                                        const float* __restrict__ him) {
    int tid  = threadIdx.x;
    int lane = tid & 31, wid = tid >> 5;
    int wg   = blockIdx.x * 8 + wid;      // 0..7167
    int as   = wg >> 4;                   // a*14+s, 0..447
    int rem  = wg & 15;
    int r    = rem >> 3;                  // 0..1
    int seg  = rem & 7;                   // 0..7 (32 RBs each)
    int a = as / 14, s = as - a * 14;

    __shared__ float red[16][8];

    float2 h[4];

#pragma unroll
    for (int t = 0; t < 4; t++) {
        int row  = ((a * 2 + r) * 4 + t) * 14 + s;
        int base = row * (F_DIM / 4) + seg * 96;      // float4 units
        const float4* pre = (const float4*)hre + base;
        const float4* pim = (const float4*)him + base;

        float4 x0 = pre[lane], x1 = pre[lane + 32], x2 = pre[lane + 64];
        float4 y0 = pim[lane], y1 = pim[lane + 32], y2 = pim[lane + 64];

        float sr0 = (x0.x + x0.y) + (x0.z + x0.w);
        float sr1 = (x1.x + x1.y) + (x1.z + x1.w);
        float sr2 = (x2.x + x2.y) + (x2.z + x2.w);
        float si0 = (y0.x + y0.y) + (y0.z + y0.w);
        float si1 = (y1.x + y1.y) + (y1.z + y1.w);
        float si2 = (y2.x + y2.y) + (y2.z + y2.w);

        // lane i needs partials q = 3i, 3i+1, 3i+2 (owner lane q&31, slot q>>5)
        float re = 0.f, im = 0.f;
#pragma unroll
        for (int j = 0; j < 3; j++) {
            int q   = 3 * lane + j;
            int src = q & 31;
            int slot = q >> 5;
            float a0 = __shfl_sync(0xffffffffu, sr0, src);
            float a1 = __shfl_sync(0xffffffffu, sr1, src);
            float a2 = __shfl_sync(0xffffffffu, sr2, src);
            float b0 = __shfl_sync(0xffffffffu, si0, src);
            float b1 = __shfl_sync(0xffffffffu, si1, src);
            float b2 = __shfl_sync(0xffffffffu, si2, src);
            re += (slot == 0) ? a0 : (slot == 1) ? a1 : a2;
            im += (slot == 0) ? b0 : (slot == 1) ? b1 : b2;
        }
        h[t] = make_float2(re * (1.0f / 12.0f), im * (1.0f / 12.0f));
    }

    // Write site data: 32B contiguous per thread (site*8 + r*4 + t layout).
    {
        int site = as * 256 + seg * 32 + lane;
        float4* dst = (float4*)(g_avg + site * 8 + r * 4);
        dst[0] = make_float4(h[0].x, h[0].y, h[1].x, h[1].y);
        dst[1] = make_float4(h[2].x, h[2].y, h[3].x, h[3].y);
    }

    // ---- Hermitian Gram partial: 4 diag (real) + 6 upper-tri (complex) ----
    float v[16];
#pragma unroll
    for (int t = 0; t < 4; t++)
        v[t] = h[t].x * h[t].x + h[t].y * h[t].y;
    {
        const int PT[6] = {0, 0, 0, 1, 1, 2};
        const int PU[6] = {1, 2, 3, 2, 3, 3};
#pragma unroll
        for (int p2 = 0; p2 < 6; p2++) {
            float2 x = h[PT[p2]], y = h[PU[p2]];
            v[4 + 2 * p2]     = x.x * y.x + x.y * y.y;   // Re(h_t conj(h_u))
            v[4 + 2 * p2 + 1] = x.y * y.x - x.x * y.y;   // Im
        }
    }

    // 16-value butterfly
    float w8[8];
    {
        bool hi = (lane & 16) != 0;
#pragma unroll
        for (int j = 0; j < 8; j++) {
            float keep = hi ? v[j + 8] : v[j];
            float send = hi ? v[j]     : v[j + 8];
            w8[j] = keep + __shfl_xor_sync(0xffffffffu, send, 16);
        }
    }
    float w4[4];
    {
        bool hi = (lane & 8) != 0;
#pragma unroll
        for (int j = 0; j < 4; j++) {
            float keep = hi ? w8[j + 4] : w8[j];
            float send = hi ? w8[j]     : w8[j + 4];
            w4[j] = keep + __shfl_xor_sync(0xffffffffu, send, 8);
        }
    }
    float w2[2];
    {
        bool hi = (lane & 4) != 0;
#pragma unroll
        for (int j = 0; j < 2; j++) {
            float k2 = hi ? w4[j + 2] : w4[j];
            float s2 = hi ? w4[j]     : w4[j + 2];
            w2[j] = k2 + __shfl_xor_sync(0xffffffffu, s2, 4);
        }
    }
    float w1;
    {
        bool hi = (lane & 2) != 0;
        float k1v = hi ? w2[1] : w2[0];
        float s1v = hi ? w2[0] : w2[1];
        w1 = k1v + __shfl_xor_sync(0xffffffffu, s1v, 2);
    }
    w1 += __shfl_xor_sync(0xffffffffu, w1, 1);
    {
        int ci = ((lane >> 4) & 1) * 8 + ((lane >> 3) & 1) * 4
               + ((lane >> 2) & 1) * 2 + ((lane >> 1) & 1);
        if ((lane & 1) == 0) red[ci][wid] = w1;
    }
    __syncthreads();

    if (tid < 16) {
        float acc = 0.f;
#pragma unroll
        for (int w = 0; w < 8; w++) acc += red[tid][w];
        atomicAdd(&g_R[tid], acc);
    }
}

// ---------------------------------------------------------------------------
// K4: per-(rb, parity-of-l) sinr/exp reduction over sites for 16 precoders.
// grid: 512 blocks (rb*2 + ch), 448 threads (one site each).
// ---------------------------------------------------------------------------
__global__ void __launch_bounds__(448) k4_sinr() {
    int b  = blockIdx.x;
    int rb = b >> 1, ch = b & 1;
    int tid  = threadIdx.x;          // 448 sites: a = tid&31, s = tid>>5
    int lane = tid & 31, wid = tid >> 5;
    int site = ((tid & 31) * 14 + (tid >> 5)) * 256 + rb;

    __shared__ float red[16][16];    // [ci][warp], 14 warps used
    __shared__ float nvs[16];        // nv' = 4*nv for local precoder ci=j*4+n

    if (tid < 16) {
        int j = tid >> 2, n = tid & 3;
        int l = 2 * j + ch;
        float sn, cs;
        __sincosf(0.78539816339744831f * (float)l, &sn, &cs);
        float pnx = (n == 0) ? 1.f : (n == 2) ? -1.f : 0.f;
        float pny = (n == 1) ? 1.f : (n == 3) ? -1.f : 0.f;
        float wx[4] = {1.f, cs, pnx, pnx * cs - pny * sn};
        float wy[4] = {0.f, sn, pny, pnx * sn + pny * cs};
        float acc = g_R[0] + g_R[1] + g_R[2] + g_R[3];
        const int PT[6] = {0, 0, 0, 1, 1, 2};
        const int PU[6] = {1, 2, 3, 2, 3, 3};
#pragma unroll
        for (int p2 = 0; p2 < 6; p2++) {
            int t = PT[p2], u = PU[p2];
            float Rre = g_R[4 + 2 * p2];
            float Rim = g_R[4 + 2 * p2 + 1];
            float zre = wx[t] * wx[u] + wy[t] * wy[u];
            float zim = wy[t] * wx[u] - wx[t] * wy[u];
            acc += 2.0f * (zre * Rre - zim * Rim);
        }
        nvs[tid] = acc * (1.0f / ((float)NSITES * SNR_LIN));
    }

    float2 h[8];
    const float4* p = (const float4*)(g_avg + site * 8);
    float4 v0 = p[0], v1 = p[1], v2 = p[2], v3 = p[3];
    h[0] = make_float2(v0.x, v0.y); h[1] = make_float2(v0.z, v0.w);
    h[2] = make_float2(v1.x, v1.y); h[3] = make_float2(v1.z, v1.w);
    h[4] = make_float2(v2.x, v2.y); h[5] = make_float2(v2.z, v2.w);
    h[6] = make_float2(v3.x, v3.y); h[7] = make_float2(v3.z, v3.w);
    __syncthreads();

    float pvv[16];

#define PV(e0x, e0y, e1x, e1y, ci) do {                                   \
        float _g  = (e0x)*(e0x) + (e0y)*(e0y) + (e1x)*(e1x) + (e1y)*(e1y);\
        float _sx = (e0x) + (e1x), _sy = (e0y) + (e1y);                   \
        float _u  = _sx * _sx + _sy * _sy;                                \
        float _nv = nvs[ci];                                              \
        float _t  = _nv * _u;                                             \
        float _Q  = fmaf(_g, _g, _t);                                     \
        float _rp = fmaf(2.0f * _t, _g + _nv, _g * _g * _g);              \
        float _si = __fdividef(_Q * _Q, _nv * _rp);                       \
        pvv[ci] = __expf(-_si * (1.0f / BETA));                           \
    } while (0)

#pragma unroll
    for (int n = 0; n < 4; n++) {
        float A0x, A0y, B0x, B0y, A1x, A1y, B1x, B1y;
        if (n == 0) {
            A0x = h[0].x + h[2].x; A0y = h[0].y + h[2].y;
            B0x = h[1].x + h[3].x; B0y = h[1].y + h[3].y;
            A1x = h[4].x + h[6].x; A1y = h[4].y + h[6].y;
            B1x = h[5].x + h[7].x; B1y = h[5].y + h[7].y;
        } else if (n == 1) {
            A0x = h[0].x - h[2].y; A0y = h[0].y + h[2].x;
            B0x = h[1].x - h[3].y; B0y = h[1].y + h[3].x;
            A1x = h[4].x - h[6].y; A1y = h[4].y + h[6].x;
            B1x = h[5].x - h[7].y; B1y = h[5].y + h[7].x;
        } else if (n == 2) {
            A0x = h[0].x - h[2].x; A0y = h[0].y - h[2].y;
            B0x = h[1].x - h[3].x; B0y = h[1].y - h[3].y;
            A1x = h[4].x - h[6].x; A1y = h[4].y - h[6].y;
            B1x = h[5].x - h[7].x; B1y = h[5].y - h[7].y;
        } else {
            A0x = h[0].x + h[2].y; A0y = h[0].y - h[2].x;
            B0x = h[1].x + h[3].y; B0y = h[1].y - h[3].x;
            A1x = h[4].x + h[6].y; A1y = h[4].y - h[6].x;
            B1x = h[5].x + h[7].y; B1y = h[5].y - h[7].x;
        }

        float D0x, D0y, D1x, D1y;
        if (ch == 0) {
            D0x = B0x; D0y = B0y; D1x = B1x; D1y = B1y;
        } else {
            D0x = SQH * (B0x - B0y); D0y = SQH * (B0y + B0x);
            D1x = SQH * (B1x - B1y); D1y = SQH * (B1y + B1x);
        }

        PV(A0x + D0x, A0y + D0y, A1x + D1x, A1y + D1y, 0 * 4 + n);
        PV(A0x - D0y, A0y + D0x, A1x - D1y, A1y + D1x, 1 * 4 + n);
        PV(A0x - D0x, A0y - D0y, A1x - D1x, A1y - D1y, 2 * 4 + n);
        PV(A0x + D0y, A0y - D0x, A1x + D1y, A1y - D1x, 3 * 4 + n);
    }
#undef PV

    // Multi-value butterfly: 16 values -> distributed sums.
    float w8[8];
    {
        bool hi = (lane & 16) != 0;
#pragma unroll
        for (int j = 0; j < 8; j++) {
            float keep = hi ? pvv[j + 8] : pvv[j];
            float send = hi ? pvv[j]     : pvv[j + 8];
            w8[j] = keep + __shfl_xor_sync(0xffffffffu, send, 16);
        }
    }
    float w4[4];
    {
        bool hi = (lane & 8) != 0;
#pragma unroll
        for (int j = 0; j < 4; j++) {
            float keep = hi ? w8[j + 4] : w8[j];
            float send = hi ? w8[j]     : w8[j + 4];
            w4[j] = keep + __shfl_xor_sync(0xffffffffu, send, 8);
        }
    }
    float w2[2];
    {
        bool hi = (lane & 4) != 0;
#pragma unroll
        for (int j = 0; j < 2; j++) {
            float k2 = hi ? w4[j + 2] : w4[j];
            float s2 = hi ? w4[j]     : w4[j + 2];
            w2[j] = k2 + __shfl_xor_sync(0xffffffffu, s2, 4);
        }
    }
    float w1;
    {
        bool hi = (lane & 2) != 0;
        float k1v = hi ? w2[1] : w2[0];
        float s1v = hi ? w2[0] : w2[1];
        w1 = k1v + __shfl_xor_sync(0xffffffffu, s1v, 2);
    }
    w1 += __shfl_xor_sync(0xffffffffu, w1, 1);
    {
        int ci = ((lane >> 4) & 1) * 8 + ((lane >> 3) & 1) * 4
               + ((lane >> 2) & 1) * 2 + ((lane >> 1) & 1);
        if ((lane & 1) == 0) red[ci][wid] = w1;
    }
    __syncthreads();

    if (tid < 16) {
        float m = 0.f;
#pragma unroll
        for (int w = 0; w < 14; w++) m += red[tid][w];
        m *= (1.0f / 448.0f);
        float avg  = -BETA * logf(m);
        float rate = 0.83f * log2f(fmaf(0.73f, avg, 1.0f));
        int j = tid >> 2, n = tid & 3;
        int c = (2 * j + ch) * 4 + n;      // global precoder index
        g_rate[rb * 32 + c] = rate;
    }
}

// ---------------------------------------------------------------------------
// K5: argmax over 32 precoders per rb + output; re-zero g_R for next replay.
// grid 32, block 256 (warp per rb).
// ---------------------------------------------------------------------------
__global__ void k5_finalize(float* __restrict__ out, int out_size) {
    int rb   = blockIdx.x * 8 + (threadIdx.x >> 5);
    int lane = threadIdx.x & 31;

    if (blockIdx.x == 0 && threadIdx.x < 16) g_R[threadIdx.x] = 0.0f;

    float best = g_rate[rb * 32 + lane];
    int   bi   = lane;
#pragma unroll
    for (int o = 16; o > 0; o >>= 1) {
        float ob = __shfl_down_sync(0xffffffffu, best, o);
        int   oi = __shfl_down_sync(0xffffffffu, bi, o);
        if (ob > best || (ob == best && oi < bi)) { best = ob; bi = oi; }
    }
    if (lane == 0) {
        out[rb]       = (float)bi;
        out[256 + rb] = best;

        int l = bi >> 2, n = bi & 3;
        float sn, cs;
        __sincosf(0.78539816339744831f * (float)l, &sn, &cs);
        float pnx = (n == 0) ? 1.f : (n == 2) ? -1.f : 0.f;
        float pny = (n == 1) ? 1.f : (n == 3) ? -1.f : 0.f;
        float wx[4] = {0.5f, 0.5f * cs, 0.5f * pnx, 0.5f * (pnx * cs - pny * sn)};
        float wy[4] = {0.0f, 0.5f * sn, 0.5f * pny, 0.5f * (pnx * sn + pny * cs)};

        if (out_size >= 2560) {
            float* pd = out + 512 + rb * 8;
#pragma unroll
            for (int t = 0; t < 4; t++) {
                pd[2 * t]     = wx[t];
                pd[2 * t + 1] = wy[t];
            }
        } else if (out_size >= 1536) {
            float* pd = out + 512 + rb * 4;
#pragma unroll
            for (int t = 0; t < 4; t++) pd[t] = wx[t];
        }
    }
}

extern "C" void kernel_launch(void* const* d_in, const int* in_sizes, int n_in,
                              void* d_out, int out_size) {
    const float* hre = (const float*)d_in[0];
    const float* him = (const float*)d_in[1];
    float* out = (float*)d_out;

    k1_rb_average<<<896, 256>>>(hre, him);
    k4_sinr<<<RB_DIM * 2, 448>>>();
    k5_finalize<<<32, 256>>>(out, out_size);
}

// round 16
// speedup vs baseline: 1.0115x; 1.0115x over previous
#include <cuda_runtime.h>

// Problem dims
#define A_DIM 32
#define R_DIM 2
#define T_DIM 4
#define S_DIM 14
#define F_DIM 3072
#define RB_DIM 256
#define NSITES (A_DIM * S_DIM * RB_DIM)   // 114688

#define BETA 2.71765f                      // 4.4492*ER^2 + 4.5655*ER + 1.2982, ER=0.25
#define SNR_LIN 10.0f
#define SQH 0.70710678118654752f

// Scratch (no allocation allowed). No cross-replay state: everything is
// overwritten every launch.
__device__ float2 g_avg[NSITES * 8];        // [site][r*4+t], site = (a*14+s)*256+rb
__device__ float  g_Rpart[896 * 16];        // per-K1-block Hermitian Gram partials
__device__ float  g_nv[32];                 // nv' = 4*nv per precoder

// ---------------------------------------------------------------------------
// K1: warp-autonomous RB-average. 896 blocks x 256 thr; each WARP owns
// (as, r, seg). Loads batched 12-deep per t-pair; partial sums regrouped via
// per-warp smem (stride-3 LDS, conflict-free) with __syncwarp only.
// Per-block Gram partial written non-atomically to g_Rpart.
// ---------------------------------------------------------------------------
__global__ void __launch_bounds__(256, 3) k1_rb_average(const float* __restrict__ hre,
                                                        const float* __restrict__ him) {
    int tid  = threadIdx.x;
    int lane = tid & 31, wid = tid >> 5;
    int wg   = blockIdx.x * 8 + wid;      // 0..7167
    int as   = wg >> 4;                   // a*14+s, 0..447
    int rem  = wg & 15;
    int r    = rem >> 3;                  // 0..1
    int seg  = rem & 7;                   // 0..7 (32 RBs each)
    int a = as / 14, s = as - a * 14;

    // per-warp stage: 2 pairs x (2 t x 2 comp x 96) = 768 floats
    __shared__ float stage[8][768];
    __shared__ float red[16][8];

    float2 h[4];

#pragma unroll
    for (int tp = 0; tp < 2; tp++) {       // t-pairs {0,1}, {2,3}
        int t0 = tp * 2;
        int row0 = ((a * 2 + r) * 4 + t0) * 14 + s;
        int row1 = row0 + 14;
        int b0 = row0 * (F_DIM / 4) + seg * 96;    // float4 units
        int b1 = row1 * (F_DIM / 4) + seg * 96;
        const float4* pre0 = (const float4*)hre + b0;
        const float4* pim0 = (const float4*)him + b0;
        const float4* pre1 = (const float4*)hre + b1;
        const float4* pim1 = (const float4*)him + b1;

        // 12 batched LDG.128
        float4 xa0 = pre0[lane], xa1 = pre0[lane + 32], xa2 = pre0[lane + 64];
        float4 ya0 = pim0[lane], ya1 = pim0[lane + 32], ya2 = pim0[lane + 64];
        float4 xb0 = pre1[lane], xb1 = pre1[lane + 32], xb2 = pre1[lane + 64];
        float4 yb0 = pim1[lane], yb1 = pim1[lane + 32], yb2 = pim1[lane + 64];

        float* w = stage[wid] + tp * 384;
        // layout within pair: [(tt*2+comp)*96 + idx]
        w[0 * 96 + lane]      = (xa0.x + xa0.y) + (xa0.z + xa0.w);
        w[0 * 96 + lane + 32] = (xa1.x + xa1.y) + (xa1.z + xa1.w);
        w[0 * 96 + lane + 64] = (xa2.x + xa2.y) + (xa2.z + xa2.w);
        w[1 * 96 + lane]      = (ya0.x + ya0.y) + (ya0.z + ya0.w);
        w[1 * 96 + lane + 32] = (ya1.x + ya1.y) + (ya1.z + ya1.w);
        w[1 * 96 + lane + 64] = (ya2.x + ya2.y) + (ya2.z + ya2.w);
        w[2 * 96 + lane]      = (xb0.x + xb0.y) + (xb0.z + xb0.w);
        w[2 * 96 + lane + 32] = (xb1.x + xb1.y) + (xb1.z + xb1.w);
        w[2 * 96 + lane + 64] = (xb2.x + xb2.y) + (xb2.z + xb2.w);
        w[3 * 96 + lane]      = (yb0.x + yb0.y) + (yb0.z + yb0.w);
        w[3 * 96 + lane + 32] = (yb1.x + yb1.y) + (yb1.z + yb1.w);
        w[3 * 96 + lane + 64] = (yb2.x + yb2.y) + (yb2.z + yb2.w);
        __syncwarp();

        int k3 = 3 * lane;
#pragma unroll
        for (int tt = 0; tt < 2; tt++) {
            float re = w[(tt * 2) * 96 + k3] + w[(tt * 2) * 96 + k3 + 1] + w[(tt * 2) * 96 + k3 + 2];
            float im = w[(tt * 2 + 1) * 96 + k3] + w[(tt * 2 + 1) * 96 + k3 + 1] + w[(tt * 2 + 1) * 96 + k3 + 2];
            h[t0 + tt] = make_float2(re * (1.0f / 12.0f), im * (1.0f / 12.0f));
        }
    }

    // Write site data: 32B contiguous per thread (site*8 + r*4 + t layout).
    {
        int site = as * 256 + seg * 32 + lane;
        float4* dst = (float4*)(g_avg + site * 8 + r * 4);
        dst[0] = make_float4(h[0].x, h[0].y, h[1].x, h[1].y);
        dst[1] = make_float4(h[2].x, h[2].y, h[3].x, h[3].y);
    }

    // ---- Hermitian Gram partial: 4 diag (real) + 6 upper-tri (complex) ----
    float v[16];
#pragma unroll
    for (int t = 0; t < 4; t++)
        v[t] = h[t].x * h[t].x + h[t].y * h[t].y;
    {
        const int PT[6] = {0, 0, 0, 1, 1, 2};
        const int PU[6] = {1, 2, 3, 2, 3, 3};
#pragma unroll
        for (int p2 = 0; p2 < 6; p2++) {
            float2 x = h[PT[p2]], y = h[PU[p2]];
            v[4 + 2 * p2]     = x.x * y.x + x.y * y.y;   // Re(h_t conj(h_u))
            v[4 + 2 * p2 + 1] = x.y * y.x - x.x * y.y;   // Im
        }
    }

    // 16-value butterfly: lanes 2k hold warp-sum of v[k']
    float w8[8];
    {
        bool hi = (lane & 16) != 0;
#pragma unroll
        for (int j = 0; j < 8; j++) {
            float keep = hi ? v[j + 8] : v[j];
            float send = hi ? v[j]     : v[j + 8];
            w8[j] = keep + __shfl_xor_sync(0xffffffffu, send, 16);
        }
    }
    float w4[4];
    {
        bool hi = (lane & 8) != 0;
#pragma unroll
        for (int j = 0; j < 4; j++) {
            float keep = hi ? w8[j + 4] : w8[j];
            float send = hi ? w8[j]     : w8[j + 4];
            w4[j] = keep + __shfl_xor_sync(0xffffffffu, send, 8);
        }
    }
    float w2[2];
    {
        bool hi = (lane & 4) != 0;
#pragma unroll
        for (int j = 0; j < 2; j++) {
            float k2 = hi ? w4[j + 2] : w4[j];
            float s2 = hi ? w4[j]     : w4[j + 2];
            w2[j] = k2 + __shfl_xor_sync(0xffffffffu, s2, 4);
        }
    }
    float w1;
    {
        bool hi = (lane & 2) != 0;
        float k1v = hi ? w2[1] : w2[0];
        float s1v = hi ? w2[0] : w2[1];
        w1 = k1v + __shfl_xor_sync(0xffffffffu, s1v, 2);
    }
    w1 += __shfl_xor_sync(0xffffffffu, w1, 1);
    {
        int ci = ((lane >> 4) & 1) * 8 + ((lane >> 3) & 1) * 4
               + ((lane >> 2) & 1) * 2 + ((lane >> 1) & 1);
        if ((lane & 1) == 0) red[ci][wid] = w1;
    }
    __syncthreads();

    if (tid < 16) {
        float acc = 0.f;
#pragma unroll
        for (int w = 0; w < 8; w++) acc += red[tid][w];
        g_Rpart[blockIdx.x * 16 + tid] = acc;
    }
}

// ---------------------------------------------------------------------------
// k_nv: reduce 896 Gram partials -> R[16], then nv'[32]. 1 block, 256 thr.
// thread = (chunk 0..15, v 0..15): sums 56 partials.
// ---------------------------------------------------------------------------
__global__ void k_nv() {
    int tid = threadIdx.x;
    int v     = tid & 15;
    int chunk = tid >> 4;            // 0..15, 56 blocks each
    __shared__ float part[16][17];
    __shared__ float R[16];

    float acc = 0.f;
    for (int b = chunk * 56; b < chunk * 56 + 56; b++)
        acc += g_Rpart[b * 16 + v];
    part[chunk][v] = acc;
    __syncthreads();

    if (tid < 16) {
        float s = 0.f;
#pragma unroll
        for (int c = 0; c < 16; c++) s += part[c][tid];
        R[tid] = s;
    }
    __syncthreads();

    if (tid < 32) {
        int c = tid;
        int l = c >> 2, n = c & 3;
        float sn, cs;
        __sincosf(0.78539816339744831f * (float)l, &sn, &cs);
        float pnx = (n == 0) ? 1.f : (n == 2) ? -1.f : 0.f;
        float pny = (n == 1) ? 1.f : (n == 3) ? -1.f : 0.f;
        float wx[4] = {1.f, cs, pnx, pnx * cs - pny * sn};
        float wy[4] = {0.f, sn, pny, pnx * sn + pny * cs};
        float acc2 = R[0] + R[1] + R[2] + R[3];
        const int PT[6] = {0, 0, 0, 1, 1, 2};
        const int PU[6] = {1, 2, 3, 2, 3, 3};
#pragma unroll
        for (int p2 = 0; p2 < 6; p2++) {
            int t = PT[p2], u = PU[p2];
            float Rre = R[4 + 2 * p2];
            float Rim = R[4 + 2 * p2 + 1];
            float zre = wx[t] * wx[u] + wy[t] * wy[u];
            float zim = wy[t] * wx[u] - wx[t] * wy[u];
            acc2 += 2.0f * (zre * Rre - zim * Rim);
        }
        g_nv[c] = acc2 * (1.0f / ((float)NSITES * SNR_LIN));
    }
}

// ---------------------------------------------------------------------------
// K45: per-rb sinr/exp reduction over 448 sites x 32 precoders, then rate,
// argmax, and output. grid 256 (one per rb), 448 threads (one site each).
// 32-value butterfly: lane L ends holding the warp sum of pvv[L].
// ---------------------------------------------------------------------------
__global__ void __launch_bounds__(448) k45_sinr_out(float* __restrict__ out, int out_size) {
    int rb   = blockIdx.x;
    int tid  = threadIdx.x;
    int lane = tid & 31, wid = tid >> 5;
    int site = ((tid & 31) * 14 + (tid >> 5)) * 256 + rb;

    __shared__ float red[32][15];    // [c][warp], 14 warps used
    __shared__ float nvs[32];

    if (tid < 32) nvs[tid] = g_nv[tid];

    float2 h[8];
    const float4* p = (const float4*)(g_avg + site * 8);
    float4 v0 = p[0], v1 = p[1], v2 = p[2], v3 = p[3];
    h[0] = make_float2(v0.x, v0.y); h[1] = make_float2(v0.z, v0.w);
    h[2] = make_float2(v1.x, v1.y); h[3] = make_float2(v1.z, v1.w);
    h[4] = make_float2(v2.x, v2.y); h[5] = make_float2(v2.z, v2.w);
    h[6] = make_float2(v3.x, v3.y); h[7] = make_float2(v3.z, v3.w);
    __syncthreads();

    float pvv[32];

#define PV(e0x, e0y, e1x, e1y, ci) do {                                   \
        float _g  = (e0x)*(e0x) + (e0y)*(e0y) + (e1x)*(e1x) + (e1y)*(e1y);\
        float _sx = (e0x) + (e1x), _sy = (e0y) + (e1y);                   \
        float _u  = _sx * _sx + _sy * _sy;                                \
        float _nv = nvs[ci];                                              \
        float _t  = _nv * _u;                                             \
        float _Q  = fmaf(_g, _g, _t);                                     \
        float _rp = fmaf(2.0f * _t, _g + _nv, _g * _g * _g);              \
        float _si = __fdividef(_Q * _Q, _nv * _rp);                       \
        pvv[ci] = __expf(-_si * (1.0f / BETA));                           \
    } while (0)

#pragma unroll
    for (int n = 0; n < 4; n++) {
        // A_r = h_r0 + phi_n h_r2 ; B_r = h_r1 + phi_n h_r3 ; phi_n = i^n
        float A0x, A0y, B0x, B0y, A1x, A1y, B1x, B1y;
        if (n == 0) {
            A0x = h[0].x + h[2].x; A0y = h[0].y + h[2].y;
            B0x = h[1].x + h[3].x; B0y = h[1].y + h[3].y;
            A1x = h[4].x + h[6].x; A1y = h[4].y + h[6].y;
            B1x = h[5].x + h[7].x; B1y = h[5].y + h[7].y;
        } else if (n == 1) {
            A0x = h[0].x - h[2].y; A0y = h[0].y + h[2].x;
            B0x = h[1].x - h[3].y; B0y = h[1].y + h[3].x;
            A1x = h[4].x - h[6].y; A1y = h[4].y + h[6].x;
            B1x = h[5].x - h[7].y; B1y = h[5].y + h[7].x;
        } else if (n == 2) {
            A0x = h[0].x - h[2].x; A0y = h[0].y - h[2].y;
            B0x = h[1].x - h[3].x; B0y = h[1].y - h[3].y;
            A1x = h[4].x - h[6].x; A1y = h[4].y - h[6].y;
            B1x = h[5].x - h[7].x; B1y = h[5].y - h[7].y;
        } else {
            A0x = h[0].x + h[2].y; A0y = h[0].y - h[2].x;
            B0x = h[1].x + h[3].y; B0y = h[1].y - h[3].x;
            A1x = h[4].x + h[6].y; A1y = h[4].y - h[6].x;
            B1x = h[5].x + h[7].y; B1y = h[5].y - h[7].x;
        }

        // even l = 2j: e_l = i^j, use D = B.  c = 8j + n
        PV(A0x + B0x, A0y + B0y, A1x + B1x, A1y + B1y, 0 + n);
        PV(A0x - B0y, A0y + B0x, A1x - B1y, A1y + B1x, 8 + n);
        PV(A0x - B0x, A0y - B0y, A1x - B1x, A1y - B1y, 16 + n);
        PV(A0x + B0y, A0y - B0x, A1x + B1y, A1y - B1x, 24 + n);

        // odd l = 2j+1: e_l = e1 * i^j, use D' = e1*B.  c = 8j + 4 + n
        float D0x = SQH * (B0x - B0y), D0y = SQH * (B0y + B0x);
        float D1x = SQH * (B1x - B1y), D1y = SQH * (B1y + B1x);
        PV(A0x + D0x, A0y + D0y, A1x + D1x, A1y + D1y, 4 + n);
        PV(A0x - D0y, A0y + D0x, A1x - D1y, A1y + D1x, 12 + n);
        PV(A0x - D0x, A0y - D0y, A1x - D1x, A1y - D1y, 20 + n);
        PV(A0x + D0y, A0y - D0x, A1x + D1y, A1y - D1x, 28 + n);
    }
#undef PV

    // 32-value butterfly: lane L ends with warp-sum of pvv[L].
    float s16[16];
    {
        bool hi = (lane & 16) != 0;
#pragma unroll
        for (int j = 0; j < 16; j++) {
            float keep = hi ? pvv[j + 16] : pvv[j];
            float send = hi ? pvv[j]      : pvv[j + 16];
            s16[j] = keep + __shfl_xor_sync(0xffffffffu, send, 16);
        }
    }
    float s8[8];
    {
        bool hi = (lane & 8) != 0;
#pragma unroll
        for (int j = 0; j < 8; j++) {
            float keep = hi ? s16[j + 8] : s16[j];
            float send = hi ? s16[j]     : s16[j + 8];
            s8[j] = keep + __shfl_xor_sync(0xffffffffu, send, 8);
        }
    }
    float s4[4];
    {
        bool hi = (lane & 4) != 0;
#pragma unroll
        for (int j = 0; j < 4; j++) {
            float keep = hi ? s4[0] : s4[0]; (void)keep;  // no-op guard
            float k2 = hi ? s8[j + 4] : s8[j];
            float s2 = hi ? s8[j]     : s8[j + 4];
            s4[j] = k2 + __shfl_xor_sync(0xffffffffu, s2, 4);
        }
    }
    float s2v[2];
    {
        bool hi = (lane & 2) != 0;
#pragma unroll
        for (int j = 0; j < 2; j++) {
            float k2 = hi ? s4[j + 2] : s4[j];
            float s2 = hi ? s4[j]     : s4[j + 2];
            s2v[j] = k2 + __shfl_xor_sync(0xffffffffu, s2, 2);
        }
    }
    float s1;
    {
        bool hi = (lane & 1) != 0;
        float k1v = hi ? s2v[1] : s2v[0];
        float s1v = hi ? s2v[0] : s2v[1];
        s1 = k1v + __shfl_xor_sync(0xffffffffu, s1v, 1);
    }
    red[lane][wid] = s1;
    __syncthreads();

    if (tid < 32) {
        int c = tid;
        float m = 0.f;
#pragma unroll
        for (int w = 0; w < 14; w++) m += red[c][w];
        m *= (1.0f / 448.0f);
        float avg  = -BETA * logf(m);
        float rate = 0.83f * log2f(fmaf(0.73f, avg, 1.0f));

        // warp argmax over the 32 rates (tid<32 == warp 0)
        float best = rate;
        int   bi   = c;
#pragma unroll
        for (int o = 16; o > 0; o >>= 1) {
            float ob = __shfl_down_sync(0xffffffffu, best, o);
            int   oi = __shfl_down_sync(0xffffffffu, bi, o);
            if (ob > best || (ob == best && oi < bi)) { best = ob; bi = oi; }
        }
        if (c == 0) {
            out[rb]       = (float)bi;
            out[256 + rb] = best;

            int l = bi >> 2, n = bi & 3;
            float sn, cs;
            __sincosf(0.78539816339744831f * (float)l, &sn, &cs);
            float pnx = (n == 0) ? 1.f : (n == 2) ? -1.f : 0.f;
            float pny = (n == 1) ? 1.f : (n == 3) ? -1.f : 0.f;
            float wx[4] = {0.5f, 0.5f * cs, 0.5f * pnx, 0.5f * (pnx * cs - pny * sn)};
            float wy[4] = {0.0f, 0.5f * sn, 0.5f * pny, 0.5f * (pnx * sn + pny * cs)};

            if (out_size >= 2560) {
                float* pd = out + 512 + rb * 8;
#pragma unroll
                for (int t = 0; t < 4; t++) {
                    pd[2 * t]     = wx[t];
                    pd[2 * t + 1] = wy[t];
                }
            } else if (out_size >= 1536) {
                float* pd = out + 512 + rb * 4;
#pragma unroll
                for (int t = 0; t < 4; t++) pd[t] = wx[t];
            }
        }
    }
}

extern "C" void kernel_launch(void* const* d_in, const int* in_sizes, int n_in,
                              void* d_out, int out_size) {
    const float* hre = (const float*)d_in[0];
    const float* him = (const float*)d_in[1];
    float* out = (float*)d_out;

    k1_rb_average<<<896, 256>>>(hre, him);
    k_nv<<<1, 256>>>();
    k45_sinr_out<<<RB_DIM, 448>>>(out, out_size);
}